// round 1
// baseline (speedup 1.0000x reference)
#include <cuda_runtime.h>

typedef unsigned long long ull;

#define NN 10000
#define F0 512
#define F1 256
#define F2 64

// ---- scratch (no cudaMalloc allowed) ----
__device__ float g_deg[NN];
__device__ float g_dis[NN];
__device__ float g_XW[NN * F1];   // X @ W1
__device__ float g_H1[NN * F1];   // layer-1 output
__device__ float g_HW[NN * F2];   // H1 @ W2
__device__ float g_Z [NN * F2];   // layer-2 output

// ---- packed f32x2 helpers (sm_100+: doubles FFMA issue rate) ----
__device__ __forceinline__ ull pack2(float x, float y) {
    ull r; asm("mov.b64 %0, {%1, %2};" : "=l"(r) : "f"(x), "f"(y)); return r;
}
__device__ __forceinline__ void fma2(ull& d, ull a, ull b) {
    asm("fma.rn.f32x2 %0, %1, %2, %0;" : "+l"(d) : "l"(a), "l"(b));
}
__device__ __forceinline__ float2 unpack2(ull v) {
    float2 r; asm("mov.b64 {%0, %1}, %2;" : "=f"(r.x), "=f"(r.y) : "l"(v)); return r;
}

// ---------------- degree / normalization ----------------
__global__ void k_deg_init() {
    int i = blockIdx.x * 256 + threadIdx.x;
    if (i < NN) g_deg[i] = 1.0f;            // self-loop contributes 1
}
__global__ void k_deg_edges(const int* __restrict__ dst, int E) {
    int i = blockIdx.x * 256 + threadIdx.x;
    if (i < E) atomicAdd(&g_deg[dst[i]], 1.0f);
}
__global__ void k_dis() {
    int i = blockIdx.x * 256 + threadIdx.x;
    if (i < NN) g_dis[i] = rsqrtf(g_deg[i]);  // deg >= 1 always
}

// ---------------- generic SGEMM: C[M,NC] = A[M,K] @ B[K,NC] ----------------
// BM=128, BN=64, BK=16, 256 threads, 8x4 microtile, f32x2 FMA.
// MODE 0: A=Xarg, C=g_XW.  MODE 1: A=g_H1, C=g_HW.
template<int K, int NC, int MODE>
__global__ void __launch_bounds__(256) k_sgemm(const float* __restrict__ Aarg,
                                               const float* __restrict__ B, int M)
{
    const float* A = (MODE == 0) ? Aarg : (const float*)g_H1;
    float*       C = (MODE == 0) ? g_XW : g_HW;

    __shared__ __align__(16) float As[16][130];  // [k][m], stride 130 (8B-aligned rows)
    __shared__ __align__(16) float Bs[16][68];   // [k][n], stride 68 (16B-aligned rows)

    int t  = threadIdx.x;
    int tx = t & 15, ty = t >> 4;
    int bm0 = blockIdx.y * 128;
    int bn0 = blockIdx.x * 64;

    ull acc[8][2];
#pragma unroll
    for (int u = 0; u < 8; ++u) { acc[u][0] = 0ull; acc[u][1] = 0ull; }

    int ar  = t >> 2;            // 0..63  (A load row)
    int akk = (t & 3) << 2;      // 0..12  (A load k)
    int bk  = t >> 4;            // 0..15  (B load k)
    int bc  = (t & 15) << 2;     // 0..60  (B load col)

    for (int k0 = 0; k0 < K; k0 += 16) {
#pragma unroll
        for (int p = 0; p < 2; ++p) {
            int row = p * 64 + ar;
            int rg  = bm0 + row;
            float4 v = make_float4(0.f, 0.f, 0.f, 0.f);
            if (rg < M) v = *(const float4*)&A[(size_t)rg * K + k0 + akk];
            As[akk + 0][row] = v.x; As[akk + 1][row] = v.y;
            As[akk + 2][row] = v.z; As[akk + 3][row] = v.w;
        }
        *(float4*)&Bs[bk][bc] = *(const float4*)&B[(size_t)(k0 + bk) * NC + bn0 + bc];
        __syncthreads();

#pragma unroll 4
        for (int k = 0; k < 16; ++k) {
            ull a2[8];
#pragma unroll
            for (int u = 0; u < 8; ++u) { float av = As[k][ty * 8 + u]; a2[u] = pack2(av, av); }
            const ull* bp = (const ull*)&Bs[k][tx * 4];
            ull b20 = bp[0], b21 = bp[1];
#pragma unroll
            for (int u = 0; u < 8; ++u) { fma2(acc[u][0], a2[u], b20); fma2(acc[u][1], a2[u], b21); }
        }
        __syncthreads();
    }

#pragma unroll
    for (int u = 0; u < 8; ++u) {
        int r = bm0 + ty * 8 + u;
        if (r < M) {
            float2 v0 = unpack2(acc[u][0]), v1 = unpack2(acc[u][1]);
            *(float4*)&C[(size_t)r * NC + bn0 + tx * 4] = make_float4(v0.x, v0.y, v1.x, v1.y);
        }
    }
}

// ---------------- H init: self-loop term + bias ----------------
// MODE 0: g_H1 = g_XW * dis^2 + b1.  MODE 1: g_Z = g_HW * dis^2 + b2.
template<int F, int MODE>
__global__ void k_init_h(const float* __restrict__ bias)
{
    const float* S = (MODE == 0) ? g_XW : g_HW;
    float*       H = (MODE == 0) ? g_H1 : g_Z;
    int i = blockIdx.x * 256 + threadIdx.x;
    if (i >= NN * F) return;
    int node = i / F;
    int f    = i & (F - 1);
    float d = g_dis[node];
    H[i] = S[i] * d * d + bias[f];
}

// ---------------- edge aggregation: H[dst] += S[src] * dis[src]*dis[dst] ----------------
// one warp per edge, float4 gathers, scalar global atomics (spread addresses -> REDG rate)
template<int F, int MODE>
__global__ void k_aggregate(const int* __restrict__ src, const int* __restrict__ dst, int E)
{
    const float* S = (MODE == 0) ? g_XW : g_HW;
    float*       H = (MODE == 0) ? g_H1 : g_Z;
    int gt = blockIdx.x * 256 + threadIdx.x;
    int e = gt >> 5, lane = gt & 31;
    if (e >= E) return;
    int s = src[e], d = dst[e];
    float nrm = g_dis[s] * g_dis[d];
    const float4* xs = (const float4*)(S + (size_t)s * F);
    float* hd = H + (size_t)d * F;
    for (int j = lane; j < F / 4; j += 32) {
        float4 v = xs[j];
        atomicAdd(hd + 4 * j + 0, v.x * nrm);
        atomicAdd(hd + 4 * j + 1, v.y * nrm);
        atomicAdd(hd + 4 * j + 2, v.z * nrm);
        atomicAdd(hd + 4 * j + 3, v.w * nrm);
    }
}

// ---------------- decoder: Y = sigmoid(Z @ Z^T), symmetric (upper tiles + mirror) ----------------
// 128x128 tile, 256 threads, 8x8 microtile, K=64 in two 32-chunks, f32x2 FMA.
__global__ void __launch_bounds__(256) k_decode(float* __restrict__ Y, int M)
{
    int bj = blockIdx.x, bi = blockIdx.y;
    if (bi > bj) return;                     // symmetric: only upper-triangular tiles

    __shared__ __align__(16) float As[32][130];
    __shared__ __align__(16) float Bs[32][130];

    int t  = threadIdx.x;
    int tx = t & 15, ty = t >> 4;

    ull acc[8][4];
#pragma unroll
    for (int u = 0; u < 8; ++u)
#pragma unroll
        for (int j = 0; j < 4; ++j) acc[u][j] = 0ull;

    int fr = t >> 3;            // 0..31 row-in-pass
    int kk = (t & 7) << 2;      // 0..28 k offset

    for (int k0 = 0; k0 < 64; k0 += 32) {
#pragma unroll
        for (int p = 0; p < 4; ++p) {
            int row = p * 32 + fr;
            int ra = bi * 128 + row;
            float4 va = make_float4(0.f, 0.f, 0.f, 0.f);
            if (ra < M) va = *(const float4*)&g_Z[ra * 64 + k0 + kk];
            As[kk + 0][row] = va.x; As[kk + 1][row] = va.y;
            As[kk + 2][row] = va.z; As[kk + 3][row] = va.w;
            int rb = bj * 128 + row;
            float4 vb = make_float4(0.f, 0.f, 0.f, 0.f);
            if (rb < M) vb = *(const float4*)&g_Z[rb * 64 + k0 + kk];
            Bs[kk + 0][row] = vb.x; Bs[kk + 1][row] = vb.y;
            Bs[kk + 2][row] = vb.z; Bs[kk + 3][row] = vb.w;
        }
        __syncthreads();

#pragma unroll 4
        for (int k = 0; k < 32; ++k) {
            ull a2[8];
#pragma unroll
            for (int u = 0; u < 8; ++u) { float av = As[k][ty * 8 + u]; a2[u] = pack2(av, av); }
            const ull* bp = (const ull*)&Bs[k][tx * 8];
            ull b0 = bp[0], b1 = bp[1], b2v = bp[2], b3 = bp[3];
#pragma unroll
            for (int u = 0; u < 8; ++u) {
                fma2(acc[u][0], a2[u], b0);
                fma2(acc[u][1], a2[u], b1);
                fma2(acc[u][2], a2[u], b2v);
                fma2(acc[u][3], a2[u], b3);
            }
        }
        __syncthreads();
    }

    float c[8][8];
#pragma unroll
    for (int u = 0; u < 8; ++u)
#pragma unroll
        for (int j = 0; j < 4; ++j) {
            float2 v = unpack2(acc[u][j]);
            c[u][2 * j] = v.x; c[u][2 * j + 1] = v.y;
        }
#pragma unroll
    for (int u = 0; u < 8; ++u)
#pragma unroll
        for (int j = 0; j < 8; ++j)
            c[u][j] = 1.0f / (1.0f + __expf(-c[u][j]));

    int r0 = bi * 128 + ty * 8;
    int c0 = bj * 128 + tx * 8;

    // normal store Y[r, c]
#pragma unroll
    for (int u = 0; u < 8; ++u) {
        int r = r0 + u;
        if (r < M) {
            if (c0 + 7 < M) {
                *(float4*)&Y[(size_t)r * M + c0]     = make_float4(c[u][0], c[u][1], c[u][2], c[u][3]);
                *(float4*)&Y[(size_t)r * M + c0 + 4] = make_float4(c[u][4], c[u][5], c[u][6], c[u][7]);
            } else {
                for (int j = 0; j < 8; ++j)
                    if (c0 + j < M) Y[(size_t)r * M + c0 + j] = c[u][j];
            }
        }
    }
    // mirrored store Y[c, r] (sigmoid(ZZ^T) is symmetric)
    if (bi != bj) {
#pragma unroll
        for (int j = 0; j < 8; ++j) {
            int cc = c0 + j;
            if (cc < M) {
                if (r0 + 7 < M) {
                    *(float4*)&Y[(size_t)cc * M + r0]     = make_float4(c[0][j], c[1][j], c[2][j], c[3][j]);
                    *(float4*)&Y[(size_t)cc * M + r0 + 4] = make_float4(c[4][j], c[5][j], c[6][j], c[7][j]);
                } else {
                    for (int u = 0; u < 8; ++u)
                        if (r0 + u < M) Y[(size_t)cc * M + r0 + u] = c[u][j];
                }
            }
        }
    }
}

// ---------------- launch ----------------
extern "C" void kernel_launch(void* const* d_in, const int* in_sizes, int n_in,
                              void* d_out, int out_size)
{
    const float* X  = (const float*)d_in[0];
    const int*   ei = (const int*)  d_in[1];
    const float* W1 = (const float*)d_in[2];
    const float* b1 = (const float*)d_in[3];
    const float* W2 = (const float*)d_in[4];
    const float* b2 = (const float*)d_in[5];
    float* Y = (float*)d_out;

    int E = in_sizes[1] / 2;
    const int* src = ei;
    const int* dst = ei + E;

    k_deg_init <<<(NN + 255) / 256, 256>>>();
    k_deg_edges<<<(E  + 255) / 256, 256>>>(dst, E);
    k_dis      <<<(NN + 255) / 256, 256>>>();

    // layer 1: H1 = agg(X @ W1) + b1    (aggregate at dim 256, not 512)
    dim3 g1(F1 / 64, (NN + 127) / 128);
    k_sgemm<F0, F1, 0><<<g1, 256>>>(X, W1, NN);
    k_init_h<F1, 0><<<(NN * F1 + 255) / 256, 256>>>(b1);
    k_aggregate<F1, 0><<<(E * 32 + 255) / 256, 256>>>(src, dst, E);

    // layer 2: Z = agg(H1 @ W2) + b2    (aggregate at dim 64, not 256)
    dim3 g2(F2 / 64, (NN + 127) / 128);
    k_sgemm<F1, F2, 1><<<g2, 256>>>(nullptr, W2, NN);
    k_init_h<F2, 1><<<(NN * F2 + 255) / 256, 256>>>(b2);
    k_aggregate<F2, 1><<<(E * 32 + 255) / 256, 256>>>(src, dst, E);

    // decoder: Y = sigmoid(Z Z^T), symmetric tiles
    dim3 gd((NN + 127) / 128, (NN + 127) / 128);
    k_decode<<<gd, 256>>>(Y, NN);
}

// round 3
// speedup vs baseline: 1.3343x; 1.3343x over previous
#include <cuda_runtime.h>

typedef unsigned long long ull;

#define NN 10000
#define F0 512
#define F1 256
#define F2 64

// ---- scratch (no cudaMalloc allowed) ----
__device__ float g_deg[NN];
__device__ float g_dis[NN];
__device__ __align__(16) float g_XW[NN * F1];   // X @ W1
__device__ __align__(16) float g_H1[NN * F1];   // layer-1 output
__device__ __align__(16) float g_HW[NN * F2];   // H1 @ W2
__device__ __align__(16) float g_Z [NN * F2];   // layer-2 output

// ---- tf32 helpers ----
__device__ __forceinline__ unsigned f2tf(float f) {
    unsigned u; asm("cvt.rna.tf32.f32 %0, %1;" : "=r"(u) : "f"(f)); return u;
}
__device__ __forceinline__ void mma_tf32(float& d0, float& d1, float& d2, float& d3,
                                         unsigned a0, unsigned a1, unsigned a2, unsigned a3,
                                         unsigned b0, unsigned b1) {
    asm volatile("mma.sync.aligned.m16n8k8.row.col.f32.tf32.tf32.f32 "
                 "{%0,%1,%2,%3}, {%4,%5,%6,%7}, {%8,%9}, {%0,%1,%2,%3};"
                 : "+f"(d0), "+f"(d1), "+f"(d2), "+f"(d3)
                 : "r"(a0), "r"(a1), "r"(a2), "r"(a3), "r"(b0), "r"(b1));
}

// ---------------- degree / normalization ----------------
__global__ void k_deg_init() {
    int i = blockIdx.x * 256 + threadIdx.x;
    if (i < NN) g_deg[i] = 1.0f;            // self-loop contributes 1
}
__global__ void k_deg_edges(const int* __restrict__ dst, int E) {
    int i = blockIdx.x * 256 + threadIdx.x;
    if (i < E) atomicAdd(&g_deg[dst[i]], 1.0f);
}
__global__ void k_dis() {
    int i = blockIdx.x * 256 + threadIdx.x;
    if (i < NN) g_dis[i] = rsqrtf(g_deg[i]);
}

// ---------------- tf32 MMA GEMM: C[M,NC] = A[M,K] @ B[K,NC] ----------------
// BM=128, BN=64, BK=32. 8 warps as 4m x 2n (warp tile 32x32).
// MODE 0: A=Xarg, C=g_XW.  MODE 1: A=g_H1, C=g_HW.
template<int K, int NC, int MODE>
__global__ void __launch_bounds__(256) k_gemm(const float* __restrict__ Aarg,
                                              const float* __restrict__ B, int M)
{
    const float* A = (MODE == 0) ? Aarg : (const float*)g_H1;
    float*       C = (MODE == 0) ? g_XW : g_HW;

    __shared__ unsigned As[128][36];  // stride 36: conflict-free frag loads
    __shared__ unsigned Bs[32][72];   // stride 72: conflict-free frag loads

    int t = threadIdx.x, lane = t & 31, wid = t >> 5;
    int wm = (wid & 3) * 32, wn = (wid >> 2) * 32;
    int g = lane >> 2, q = lane & 3;
    int bm0 = blockIdx.y * 128, bn0 = blockIdx.x * 64;

    float acc[2][4][4];
#pragma unroll
    for (int i = 0; i < 2; ++i)
#pragma unroll
        for (int j = 0; j < 4; ++j)
#pragma unroll
            for (int x = 0; x < 4; ++x) acc[i][j][x] = 0.f;

    for (int k0 = 0; k0 < K; k0 += 32) {
        // load A tile 128x32 (coalesced float4, cvt to tf32)
#pragma unroll
        for (int it = 0; it < 4; ++it) {
            int idx = t + it * 256;          // 1024 float4s: 128 rows x 8
            int row = idx >> 3, c4 = (idx & 7) << 2;
            float4 v = make_float4(0.f, 0.f, 0.f, 0.f);
            int rg = bm0 + row;
            if (rg < M) v = *(const float4*)&A[(size_t)rg * K + k0 + c4];
            *(uint4*)&As[row][c4] = make_uint4(f2tf(v.x), f2tf(v.y), f2tf(v.z), f2tf(v.w));
        }
        // load B tile 32x64
#pragma unroll
        for (int it = 0; it < 2; ++it) {
            int idx = t + it * 256;          // 512 float4s: 32 rows x 16
            int row = idx >> 4, c4 = (idx & 15) << 2;
            float4 v = *(const float4*)&B[(size_t)(k0 + row) * NC + bn0 + c4];
            *(uint4*)&Bs[row][c4] = make_uint4(f2tf(v.x), f2tf(v.y), f2tf(v.z), f2tf(v.w));
        }
        __syncthreads();

#pragma unroll
        for (int ks = 0; ks < 4; ++ks) {
            int kk = ks * 8;
            unsigned bf[4][2];
#pragma unroll
            for (int j = 0; j < 4; ++j) {
                bf[j][0] = Bs[kk + q][wn + j * 8 + g];
                bf[j][1] = Bs[kk + q + 4][wn + j * 8 + g];
            }
#pragma unroll
            for (int i = 0; i < 2; ++i) {
                int r = wm + i * 16 + g;
                unsigned a0 = As[r][kk + q],     a1 = As[r + 8][kk + q];
                unsigned a2 = As[r][kk + q + 4], a3 = As[r + 8][kk + q + 4];
#pragma unroll
                for (int j = 0; j < 4; ++j)
                    mma_tf32(acc[i][j][0], acc[i][j][1], acc[i][j][2], acc[i][j][3],
                             a0, a1, a2, a3, bf[j][0], bf[j][1]);
            }
        }
        __syncthreads();
    }

#pragma unroll
    for (int i = 0; i < 2; ++i) {
#pragma unroll
        for (int j = 0; j < 4; ++j) {
            int c  = bn0 + wn + j * 8 + q * 2;
            int r0 = bm0 + wm + i * 16 + g;
            if (r0 < M)     *(float2*)&C[(size_t)r0 * NC + c]       = make_float2(acc[i][j][0], acc[i][j][1]);
            if (r0 + 8 < M) *(float2*)&C[(size_t)(r0 + 8) * NC + c] = make_float2(acc[i][j][2], acc[i][j][3]);
        }
    }
}

// ---------------- H init: self-loop term + bias ----------------
template<int F, int MODE>
__global__ void k_init_h(const float* __restrict__ bias)
{
    const float* S = (MODE == 0) ? g_XW : g_HW;
    float*       H = (MODE == 0) ? g_H1 : g_Z;
    int i = blockIdx.x * 256 + threadIdx.x;
    if (i >= NN * F) return;
    int node = i / F;
    int f    = i & (F - 1);
    float d = g_dis[node];
    H[i] = S[i] * d * d + bias[f];
}

// ---------------- edge aggregation: H[dst] += S[src] * dis[src]*dis[dst] ----------------
template<int F, int MODE>
__global__ void k_aggregate(const int* __restrict__ src, const int* __restrict__ dst, int E)
{
    const float* S = (MODE == 0) ? g_XW : g_HW;
    float*       H = (MODE == 0) ? g_H1 : g_Z;
    int gt = blockIdx.x * 256 + threadIdx.x;
    int e = gt >> 5, lane = gt & 31;
    if (e >= E) return;
    int s = src[e], d = dst[e];
    float nrm = g_dis[s] * g_dis[d];
    const float4* xs = (const float4*)(S + (size_t)s * F);
    float* hd = H + (size_t)d * F;
    for (int j = lane; j < F / 4; j += 32) {
        float4 v = xs[j];
        atomicAdd(hd + 4 * j + 0, v.x * nrm);
        atomicAdd(hd + 4 * j + 1, v.y * nrm);
        atomicAdd(hd + 4 * j + 2, v.z * nrm);
        atomicAdd(hd + 4 * j + 3, v.w * nrm);
    }
}

// ---------------- decoder: Y = sigmoid(Z @ Z^T), tf32 MMA, symmetric ----------------
// 128x128 tile, K=64 fully resident. 8 warps as 4m x 2n (warp tile 32x64).
#define DEC_SMEM (128*68*4 + 64*136*4)   // 69632 bytes (T[128][132]=67584 reuses it)
__global__ void __launch_bounds__(256) k_decode(float* __restrict__ Y, int M)
{
    int bj = blockIdx.x, bi = blockIdx.y;
    if (bi > bj) return;                  // symmetric: upper-triangular tiles only

    extern __shared__ unsigned char sraw[];
    unsigned (*As)[68]  = (unsigned(*)[68])sraw;                  // [128][68]
    unsigned (*Bs)[136] = (unsigned(*)[136])(sraw + 128*68*4);    // [64][136]
    float* T = (float*)sraw;                                      // [128][132] (phase 2)

    int t = threadIdx.x, lane = t & 31, wid = t >> 5;
    int wm = (wid & 3) * 32, wn = (wid >> 2) * 64;
    int g = lane >> 2, q = lane & 3;
    int r0b = bi * 128, c0b = bj * 128;

    // A tile: Z rows of block-i (coalesced)
#pragma unroll
    for (int it = 0; it < 8; ++it) {
        int idx = t + it * 256;           // 2048: 128 rows x 16 float4
        int row = idx >> 4, c4 = (idx & 15) << 2;
        float4 v = make_float4(0.f, 0.f, 0.f, 0.f);
        if (r0b + row < M) v = *(const float4*)&g_Z[(r0b + row) * 64 + c4];
        *(uint4*)&As[row][c4] = make_uint4(f2tf(v.x), f2tf(v.y), f2tf(v.z), f2tf(v.w));
    }
    // B tile transposed: Bs[k][col] = Z[c0b+col][k]
#pragma unroll
    for (int it = 0; it < 8; ++it) {
        int idx = t + it * 256;
        int col = idx & 127, c4 = (idx >> 7) << 2;
        float4 v = make_float4(0.f, 0.f, 0.f, 0.f);
        if (c0b + col < M) v = *(const float4*)&g_Z[(c0b + col) * 64 + c4];
        Bs[c4 + 0][col] = f2tf(v.x); Bs[c4 + 1][col] = f2tf(v.y);
        Bs[c4 + 2][col] = f2tf(v.z); Bs[c4 + 3][col] = f2tf(v.w);
    }
    __syncthreads();

    float acc[2][8][4];
#pragma unroll
    for (int i = 0; i < 2; ++i)
#pragma unroll
        for (int j = 0; j < 8; ++j)
#pragma unroll
            for (int x = 0; x < 4; ++x) acc[i][j][x] = 0.f;

#pragma unroll
    for (int ks = 0; ks < 8; ++ks) {
        int kk = ks * 8;
        unsigned bf[8][2];
#pragma unroll
        for (int j = 0; j < 8; ++j) {
            bf[j][0] = Bs[kk + q][wn + j * 8 + g];
            bf[j][1] = Bs[kk + q + 4][wn + j * 8 + g];
        }
#pragma unroll
        for (int i = 0; i < 2; ++i) {
            int r = wm + i * 16 + g;
            unsigned a0 = As[r][kk + q],     a1 = As[r + 8][kk + q];
            unsigned a2 = As[r][kk + q + 4], a3 = As[r + 8][kk + q + 4];
#pragma unroll
            for (int j = 0; j < 8; ++j)
                mma_tf32(acc[i][j][0], acc[i][j][1], acc[i][j][2], acc[i][j][3],
                         a0, a1, a2, a3, bf[j][0], bf[j][1]);
        }
    }

    // sigmoid
#pragma unroll
    for (int i = 0; i < 2; ++i)
#pragma unroll
        for (int j = 0; j < 8; ++j)
#pragma unroll
            for (int x = 0; x < 4; ++x)
                acc[i][j][x] = 1.0f / (1.0f + __expf(-acc[i][j][x]));

    // normal store Y[r][c] directly from fragments (float2, 32B/row sectors)
#pragma unroll
    for (int i = 0; i < 2; ++i) {
        int r = r0b + wm + i * 16 + g;
#pragma unroll
        for (int j = 0; j < 8; ++j) {
            int c = c0b + wn + j * 8 + q * 2;
            if (c < M) {   // c is even, so c+1 <= M-1 whenever c < M
                if (r < M)     *(float2*)&Y[(size_t)r * M + c]       = make_float2(acc[i][j][0], acc[i][j][1]);
                if (r + 8 < M) *(float2*)&Y[(size_t)(r + 8) * M + c] = make_float2(acc[i][j][2], acc[i][j][3]);
            }
        }
    }

    // mirrored store via smem transpose (coalesced float4 rows of Y)
    if (bi != bj) {
        __syncthreads();                     // everyone done reading As/Bs
#pragma unroll
        for (int i = 0; i < 2; ++i) {
#pragma unroll
            for (int j = 0; j < 8; ++j) {
                int cc = wn + j * 8 + q * 2;   // local col
                int rr = wm + i * 16 + g;      // local row
                T[cc * 132 + rr]           = acc[i][j][0];
                T[(cc + 1) * 132 + rr]     = acc[i][j][1];
                T[cc * 132 + rr + 8]       = acc[i][j][2];
                T[(cc + 1) * 132 + rr + 8] = acc[i][j][3];
            }
        }
        __syncthreads();
#pragma unroll
        for (int it = 0; it < 16; ++it) {
            int idx = t + it * 256;          // 4096 = 128 cols x 32 row-chunks
            int cc = idx >> 5, rc = (idx & 31) << 2;
            int crow = c0b + cc;
            if (crow < M) {
                float4 v = *(const float4*)&T[cc * 132 + rc];
                if (r0b + rc + 3 < M) {
                    *(float4*)&Y[(size_t)crow * M + r0b + rc] = v;
                } else {
                    float vv[4] = {v.x, v.y, v.z, v.w};
                    for (int j = 0; j < 4; ++j)
                        if (r0b + rc + j < M) Y[(size_t)crow * M + r0b + rc + j] = vv[j];
                }
            }
        }
    }
}

// ---------------- launch ----------------
extern "C" void kernel_launch(void* const* d_in, const int* in_sizes, int n_in,
                              void* d_out, int out_size)
{
    const float* X  = (const float*)d_in[0];
    const int*   ei = (const int*)  d_in[1];
    const float* W1 = (const float*)d_in[2];
    const float* b1 = (const float*)d_in[3];
    const float* W2 = (const float*)d_in[4];
    const float* b2 = (const float*)d_in[5];
    float* Y = (float*)d_out;

    int E = in_sizes[1] / 2;
    const int* src = ei;
    const int* dst = ei + E;

    static bool attr_done = false;
    if (!attr_done) {
        cudaFuncSetAttribute(k_decode, cudaFuncAttributeMaxDynamicSharedMemorySize, DEC_SMEM);
        attr_done = true;   // idempotent attr, not work — graph-capture safe
    }

    k_deg_init <<<(NN + 255) / 256, 256>>>();
    k_deg_edges<<<(E  + 255) / 256, 256>>>(dst, E);
    k_dis      <<<(NN + 255) / 256, 256>>>();

    // layer 1: H1 = agg(X @ W1) + b1   (aggregate at dim 256)
    dim3 g1(F1 / 64, (NN + 127) / 128);
    k_gemm<F0, F1, 0><<<g1, 256>>>(X, W1, NN);
    k_init_h<F1, 0><<<(NN * F1 + 255) / 256, 256>>>(b1);
    k_aggregate<F1, 0><<<(E * 32 + 255) / 256, 256>>>(src, dst, E);

    // layer 2: Z = agg(H1 @ W2) + b2   (aggregate at dim 64)
    dim3 g2(F2 / 64, (NN + 127) / 128);
    k_gemm<F1, F2, 1><<<g2, 256>>>(nullptr, W2, NN);
    k_init_h<F2, 1><<<(NN * F2 + 255) / 256, 256>>>(b2);
    k_aggregate<F2, 1><<<(E * 32 + 255) / 256, 256>>>(src, dst, E);

    // decoder: Y = sigmoid(Z Z^T)  -- FIX: pass dynamic smem size at launch
    dim3 gd((NN + 127) / 128, (NN + 127) / 128);
    k_decode<<<gd, 256, DEC_SMEM>>>(Y, NN);
}

// round 4
// speedup vs baseline: 2.3396x; 1.7535x over previous
#include <cuda_runtime.h>
#include <math.h>

#define NN 10000
#define NE 320000
#define F0 512
#define F1 256
#define F2 64
#define NB 79            // ceil(10000/128)

// ---- scratch (no cudaMalloc allowed) ----
__device__ int   g_cnt[NN];
__device__ int   g_ptr[NN + 1];
__device__ int   g_cur[NN];
__device__ int   g_csr[NE];
__device__ float g_dis[NN];
__device__ __align__(16) float g_XW[NN * F1];   // (X @ W1) * dis[row]
__device__ __align__(16) float g_H1[NN * F1];   // layer-1 output
__device__ __align__(16) float g_HW[NN * F2];   // (H1 @ W2) * dis[row]
__device__ __align__(16) float g_Z [NN * F2];   // layer-2 output

// ---- tf32 / cp.async helpers ----
__device__ __forceinline__ unsigned f2tf(float f) {
    unsigned u; asm("cvt.rna.tf32.f32 %0, %1;" : "=r"(u) : "f"(f)); return u;
}
__device__ __forceinline__ void mma_tf32(float& d0, float& d1, float& d2, float& d3,
                                         unsigned a0, unsigned a1, unsigned a2, unsigned a3,
                                         unsigned b0, unsigned b1) {
    asm volatile("mma.sync.aligned.m16n8k8.row.col.f32.tf32.tf32.f32 "
                 "{%0,%1,%2,%3}, {%4,%5,%6,%7}, {%8,%9}, {%0,%1,%2,%3};"
                 : "+f"(d0), "+f"(d1), "+f"(d2), "+f"(d3)
                 : "r"(a0), "r"(a1), "r"(a2), "r"(a3), "r"(b0), "r"(b1));
}
__device__ __forceinline__ void cpa16(float* dst_smem, const float* src, bool pred) {
    unsigned sa = (unsigned)__cvta_generic_to_shared(dst_smem);
    int sz = pred ? 16 : 0;
    asm volatile("cp.async.cg.shared.global [%0], [%1], 16, %2;" :: "r"(sa), "l"(src), "r"(sz));
}
#define CP_COMMIT() asm volatile("cp.async.commit_group;")
#define CP_WAIT1()  asm volatile("cp.async.wait_group 1;")

// ================= CSR build =================
__global__ void k_zero() {
    int i = blockIdx.x * 256 + threadIdx.x;
    if (i < NN) g_cnt[i] = 0;
}
__global__ void k_count(const int* __restrict__ dst, int E) {
    int i = blockIdx.x * 256 + threadIdx.x;
    if (i < E) atomicAdd(&g_cnt[dst[i]], 1);
}
// single block: exclusive scan of cnt -> ptr/cur, plus dis = rsqrt(cnt+1)
__global__ void __launch_bounds__(1024) k_scan() {
    __shared__ int sh[1024];
    __shared__ int carry_s;
    int t = threadIdx.x;
    if (t == 0) carry_s = 0;
    __syncthreads();
    for (int base = 0; base < NN; base += 1024) {
        int i = base + t;
        int v = (i < NN) ? g_cnt[i] : 0;
        sh[t] = v; __syncthreads();
        for (int off = 1; off < 1024; off <<= 1) {
            int x = (t >= off) ? sh[t - off] : 0;
            __syncthreads();
            sh[t] += x;
            __syncthreads();
        }
        int excl = carry_s + sh[t] - v;
        if (i < NN) {
            g_ptr[i] = excl;
            g_cur[i] = excl;
            g_dis[i] = rsqrtf((float)(v + 1));
        }
        __syncthreads();
        if (t == 1023) carry_s += sh[1023];
        __syncthreads();
    }
    if (t == 0) g_ptr[NN] = carry_s;
}
__global__ void k_scatter(const int* __restrict__ src, const int* __restrict__ dst, int E) {
    int i = blockIdx.x * 256 + threadIdx.x;
    if (i < E) {
        int pos = atomicAdd(&g_cur[dst[i]], 1);
        g_csr[pos] = src[i];
    }
}

// ================= tf32 GEMM, cp.async double-buffered =================
// C[r] = (A[r] @ B) * dis[r].  BM=128, BN=64, BK=32, 8 warps (4m x 2n).
#define GEMM_SMEM ((2*128*36 + 2*32*72) * 4)
template<int K, int NC, int MODE>
__global__ void __launch_bounds__(256) k_gemm(const float* __restrict__ Aarg,
                                              const float* __restrict__ B, int M)
{
    const float* A = (MODE == 0) ? Aarg : (const float*)g_H1;
    float*       C = (MODE == 0) ? g_XW : g_HW;

    extern __shared__ float gsm[];
    float* Asm = gsm;                    // [2][128][36]
    float* Bsm = gsm + 2 * 128 * 36;     // [2][32][72]
#define ASF(s, r, c) Asm[(s) * (128 * 36) + (r) * 36 + (c)]
#define BSF(s, r, c) Bsm[(s) * (32 * 72) + (r) * 72 + (c)]

    int t = threadIdx.x, lane = t & 31, wid = t >> 5;
    int wm = (wid & 3) * 32, wn = (wid >> 2) * 32;
    int g = lane >> 2, q = lane & 3;
    int bm0 = blockIdx.y * 128, bn0 = blockIdx.x * 64;

    float acc[2][4][4];
#pragma unroll
    for (int i = 0; i < 2; ++i)
#pragma unroll
        for (int j = 0; j < 4; ++j)
#pragma unroll
            for (int x = 0; x < 4; ++x) acc[i][j][x] = 0.f;

    const int KT = K / 32;

    auto load_tile = [&](int kt, int s) {
#pragma unroll
        for (int it = 0; it < 4; ++it) {            // A: 128x32 = 1024 float4
            int idx = t + it * 256;
            int row = idx >> 3, c4 = (idx & 7) << 2;
            int rg = bm0 + row;
            bool ok = rg < M;
            const float* sp = &A[(size_t)(ok ? rg : 0) * K + kt * 32 + c4];
            cpa16(&ASF(s, row, c4), sp, ok);
        }
#pragma unroll
        for (int it = 0; it < 2; ++it) {            // B: 32x64 = 512 float4
            int idx = t + it * 256;
            int row = idx >> 4, c4 = (idx & 15) << 2;
            cpa16(&BSF(s, row, c4), &B[(size_t)(kt * 32 + row) * NC + bn0 + c4], true);
        }
    };

    load_tile(0, 0);
    CP_COMMIT();

    for (int kt = 0; kt < KT; ++kt) {
        int cb = kt & 1;
        if (kt + 1 < KT) load_tile(kt + 1, cb ^ 1);
        CP_COMMIT();
        CP_WAIT1();
        __syncthreads();

#pragma unroll
        for (int ks = 0; ks < 4; ++ks) {
            int kk = ks * 8;
            unsigned bf[4][2];
#pragma unroll
            for (int j = 0; j < 4; ++j) {
                bf[j][0] = f2tf(BSF(cb, kk + q,     wn + j * 8 + g));
                bf[j][1] = f2tf(BSF(cb, kk + q + 4, wn + j * 8 + g));
            }
#pragma unroll
            for (int i = 0; i < 2; ++i) {
                int r = wm + i * 16 + g;
                unsigned a0 = f2tf(ASF(cb, r,     kk + q));
                unsigned a1 = f2tf(ASF(cb, r + 8, kk + q));
                unsigned a2 = f2tf(ASF(cb, r,     kk + q + 4));
                unsigned a3 = f2tf(ASF(cb, r + 8, kk + q + 4));
#pragma unroll
                for (int j = 0; j < 4; ++j)
                    mma_tf32(acc[i][j][0], acc[i][j][1], acc[i][j][2], acc[i][j][3],
                             a0, a1, a2, a3, bf[j][0], bf[j][1]);
            }
        }
        __syncthreads();
    }

#pragma unroll
    for (int i = 0; i < 2; ++i) {
        int r0 = bm0 + wm + i * 16 + g;
        float ds0 = (r0 < M)     ? g_dis[r0]     : 0.f;
        float ds1 = (r0 + 8 < M) ? g_dis[r0 + 8] : 0.f;
#pragma unroll
        for (int j = 0; j < 4; ++j) {
            int c = bn0 + wn + j * 8 + q * 2;
            if (r0 < M)     *(float2*)&C[(size_t)r0 * NC + c]       = make_float2(acc[i][j][0] * ds0, acc[i][j][1] * ds0);
            if (r0 + 8 < M) *(float2*)&C[(size_t)(r0 + 8) * NC + c] = make_float2(acc[i][j][2] * ds1, acc[i][j][3] * ds1);
        }
    }
#undef ASF
#undef BSF
}

// ================= CSR aggregation (no atomics) =================
// F=256: one block per node, thread = feature. H1[d] = dis[d]*(sum + self) + b1
__global__ void __launch_bounds__(256) k_agg256(const float* __restrict__ bias)
{
    int d = blockIdx.x;
    int t = threadIdx.x;
    float acc = g_XW[(size_t)d * 256 + t];          // self term (XW' = XW*dis)
    int e0 = g_ptr[d], e1 = g_ptr[d + 1];
    int e = e0;
    for (; e + 1 < e1; e += 2) {
        int s0 = g_csr[e], s1 = g_csr[e + 1];
        acc += g_XW[(size_t)s0 * 256 + t] + g_XW[(size_t)s1 * 256 + t];
    }
    if (e < e1) acc += g_XW[(size_t)g_csr[e] * 256 + t];
    g_H1[(size_t)d * 256 + t] = acc * g_dis[d] + bias[t];
}
// F=64: one warp per node, lane holds float2. Z[d] = dis[d]*(sum + self) + b2
__global__ void __launch_bounds__(256) k_agg64(const float* __restrict__ bias)
{
    int gt = blockIdx.x * 256 + threadIdx.x;
    int d = gt >> 5, lane = gt & 31;
    if (d >= NN) return;
    float2 acc = *(const float2*)&g_HW[(size_t)d * 64 + lane * 2];
    int e0 = g_ptr[d], e1 = g_ptr[d + 1];
    int e = e0;
    for (; e + 1 < e1; e += 2) {
        int s0 = g_csr[e], s1 = g_csr[e + 1];
        float2 v0 = *(const float2*)&g_HW[(size_t)s0 * 64 + lane * 2];
        float2 v1 = *(const float2*)&g_HW[(size_t)s1 * 64 + lane * 2];
        acc.x += v0.x + v1.x; acc.y += v0.y + v1.y;
    }
    if (e < e1) {
        float2 v = *(const float2*)&g_HW[(size_t)g_csr[e] * 64 + lane * 2];
        acc.x += v.x; acc.y += v.y;
    }
    float dd = g_dis[d];
    float2 b = *(const float2*)&bias[lane * 2];
    *(float2*)&g_Z[(size_t)d * 64 + lane * 2] = make_float2(acc.x * dd + b.x, acc.y * dd + b.y);
}

// ================= decoder: Y = sigmoid(Z Z^T), tf32, triangular grid =================
#define DEC_SMEM (128*68*4 + 64*136*4)   // 69632 B; T[128][132] reuses it
__global__ void __launch_bounds__(256) k_decode(float* __restrict__ Y, int M)
{
    // linear tile id -> (bi, bj), bi <= bj
    int k = blockIdx.x;
    int bi = (int)((2.0f * NB + 1.0f - sqrtf((2.0f * NB + 1.0f) * (2.0f * NB + 1.0f) - 8.0f * k)) * 0.5f);
    if (bi < 0) bi = 0;
    while (bi * NB - bi * (bi - 1) / 2 > k) --bi;
    while ((bi + 1) * NB - (bi + 1) * bi / 2 <= k) ++bi;
    int bj = bi + (k - (bi * NB - bi * (bi - 1) / 2));

    extern __shared__ unsigned char sraw[];
    unsigned (*As)[68]  = (unsigned(*)[68])sraw;                  // [128][68]
    unsigned (*Bs)[136] = (unsigned(*)[136])(sraw + 128*68*4);    // [64][136]
    float* T = (float*)sraw;                                      // [128][132] phase 2

    int t = threadIdx.x, lane = t & 31, wid = t >> 5;
    int wm = (wid & 3) * 32, wn = (wid >> 2) * 64;
    int g = lane >> 2, q = lane & 3;
    int r0b = bi * 128, c0b = bj * 128;

#pragma unroll
    for (int it = 0; it < 8; ++it) {
        int idx = t + it * 256;           // 2048: 128 rows x 16 float4
        int row = idx >> 4, c4 = (idx & 15) << 2;
        float4 v = make_float4(0.f, 0.f, 0.f, 0.f);
        if (r0b + row < M) v = *(const float4*)&g_Z[(r0b + row) * 64 + c4];
        *(uint4*)&As[row][c4] = make_uint4(f2tf(v.x), f2tf(v.y), f2tf(v.z), f2tf(v.w));
    }
#pragma unroll
    for (int it = 0; it < 8; ++it) {
        int idx = t + it * 256;
        int col = idx & 127, c4 = (idx >> 7) << 2;
        float4 v = make_float4(0.f, 0.f, 0.f, 0.f);
        if (c0b + col < M) v = *(const float4*)&g_Z[(c0b + col) * 64 + c4];
        Bs[c4 + 0][col] = f2tf(v.x); Bs[c4 + 1][col] = f2tf(v.y);
        Bs[c4 + 2][col] = f2tf(v.z); Bs[c4 + 3][col] = f2tf(v.w);
    }
    __syncthreads();

    float acc[2][8][4];
#pragma unroll
    for (int i = 0; i < 2; ++i)
#pragma unroll
        for (int j = 0; j < 8; ++j)
#pragma unroll
            for (int x = 0; x < 4; ++x) acc[i][j][x] = 0.f;

#pragma unroll
    for (int ks = 0; ks < 8; ++ks) {
        int kk = ks * 8;
        unsigned bf[8][2];
#pragma unroll
        for (int j = 0; j < 8; ++j) {
            bf[j][0] = Bs[kk + q][wn + j * 8 + g];
            bf[j][1] = Bs[kk + q + 4][wn + j * 8 + g];
        }
#pragma unroll
        for (int i = 0; i < 2; ++i) {
            int r = wm + i * 16 + g;
            unsigned a0 = As[r][kk + q],     a1 = As[r + 8][kk + q];
            unsigned a2 = As[r][kk + q + 4], a3 = As[r + 8][kk + q + 4];
#pragma unroll
            for (int j = 0; j < 8; ++j)
                mma_tf32(acc[i][j][0], acc[i][j][1], acc[i][j][2], acc[i][j][3],
                         a0, a1, a2, a3, bf[j][0], bf[j][1]);
        }
    }

#pragma unroll
    for (int i = 0; i < 2; ++i)
#pragma unroll
        for (int j = 0; j < 8; ++j)
#pragma unroll
            for (int x = 0; x < 4; ++x)
                acc[i][j][x] = 1.0f / (1.0f + __expf(-acc[i][j][x]));

    // normal store Y[r][c]
#pragma unroll
    for (int i = 0; i < 2; ++i) {
        int r = r0b + wm + i * 16 + g;
#pragma unroll
        for (int j = 0; j < 8; ++j) {
            int c = c0b + wn + j * 8 + q * 2;
            if (c < M) {
                if (r < M)     *(float2*)&Y[(size_t)r * M + c]       = make_float2(acc[i][j][0], acc[i][j][1]);
                if (r + 8 < M) *(float2*)&Y[(size_t)(r + 8) * M + c] = make_float2(acc[i][j][2], acc[i][j][3]);
            }
        }
    }

    // mirrored store via smem transpose
    if (bi != bj) {
        __syncthreads();
#pragma unroll
        for (int i = 0; i < 2; ++i) {
#pragma unroll
            for (int j = 0; j < 8; ++j) {
                int cc = wn + j * 8 + q * 2;
                int rr = wm + i * 16 + g;
                T[cc * 132 + rr]           = acc[i][j][0];
                T[(cc + 1) * 132 + rr]     = acc[i][j][1];
                T[cc * 132 + rr + 8]       = acc[i][j][2];
                T[(cc + 1) * 132 + rr + 8] = acc[i][j][3];
            }
        }
        __syncthreads();
#pragma unroll
        for (int it = 0; it < 16; ++it) {
            int idx = t + it * 256;
            int cc = idx >> 5, rc = (idx & 31) << 2;
            int crow = c0b + cc;
            if (crow < M) {
                float4 v = *(const float4*)&T[cc * 132 + rc];
                if (r0b + rc + 3 < M) {
                    *(float4*)&Y[(size_t)crow * M + r0b + rc] = v;
                } else {
                    float vv[4] = {v.x, v.y, v.z, v.w};
                    for (int j = 0; j < 4; ++j)
                        if (r0b + rc + j < M) Y[(size_t)crow * M + r0b + rc + j] = vv[j];
                }
            }
        }
    }
}

// ================= launch =================
extern "C" void kernel_launch(void* const* d_in, const int* in_sizes, int n_in,
                              void* d_out, int out_size)
{
    const float* X  = (const float*)d_in[0];
    const int*   ei = (const int*)  d_in[1];
    const float* W1 = (const float*)d_in[2];
    const float* b1 = (const float*)d_in[3];
    const float* W2 = (const float*)d_in[4];
    const float* b2 = (const float*)d_in[5];
    float* Y = (float*)d_out;

    int E = in_sizes[1] / 2;
    if (E > NE) E = NE;
    const int* src = ei;
    const int* dst = ei + E;

    static bool attr_done = false;
    if (!attr_done) {
        cudaFuncSetAttribute(k_decode, cudaFuncAttributeMaxDynamicSharedMemorySize, DEC_SMEM);
        cudaFuncSetAttribute(k_gemm<F0, F1, 0>, cudaFuncAttributeMaxDynamicSharedMemorySize, GEMM_SMEM);
        cudaFuncSetAttribute(k_gemm<F1, F2, 1>, cudaFuncAttributeMaxDynamicSharedMemorySize, GEMM_SMEM);
        attr_done = true;
    }

    // CSR build + dis
    k_zero   <<<(NN + 255) / 256, 256>>>();
    k_count  <<<(E  + 255) / 256, 256>>>(dst, E);
    k_scan   <<<1, 1024>>>();
    k_scatter<<<(E  + 255) / 256, 256>>>(src, dst, E);

    // layer 1
    dim3 g1(F1 / 64, (NN + 127) / 128);
    k_gemm<F0, F1, 0><<<g1, 256, GEMM_SMEM>>>(X, W1, NN);
    k_agg256<<<NN, 256>>>(b1);

    // layer 2
    dim3 g2(F2 / 64, (NN + 127) / 128);
    k_gemm<F1, F2, 1><<<g2, 256, GEMM_SMEM>>>(nullptr, W2, NN);
    k_agg64<<<(NN * 32 + 255) / 256, 256>>>(b2);

    // decoder (triangular grid)
    k_decode<<<NB * (NB + 1) / 2, 256, DEC_SMEM>>>(Y, NN);
}

// round 6
// speedup vs baseline: 2.6076x; 1.1145x over previous
#include <cuda_runtime.h>
#include <math.h>

#define NN 10000
#define NE 320000
#define F0 512
#define F1 256
#define F2 64
#define NB 79            // ceil(10000/128)

// ---- scratch (no cudaMalloc allowed) ----
__device__ int   g_cnt[NN];
__device__ int   g_ptr[NN + 1];
__device__ int   g_cur[NN];
__device__ int   g_csr[NE];
__device__ float g_dis[NN];
__device__ __align__(16) float g_XW[NN * F1];   // X @ W1   (unscaled!)
__device__ __align__(16) float g_H1[NN * F1];   // layer-1 output
__device__ __align__(16) float g_HW[NN * F2];   // H1 @ W2  (unscaled!)
__device__ __align__(16) float g_Z [NN * F2];   // layer-2 output

// ---- tf32 / cp.async helpers ----
__device__ __forceinline__ unsigned f2tf(float f) {
    unsigned u; asm("cvt.rna.tf32.f32 %0, %1;" : "=r"(u) : "f"(f)); return u;
}
__device__ __forceinline__ void mma_tf32(float& d0, float& d1, float& d2, float& d3,
                                         unsigned a0, unsigned a1, unsigned a2, unsigned a3,
                                         unsigned b0, unsigned b1) {
    asm volatile("mma.sync.aligned.m16n8k8.row.col.f32.tf32.tf32.f32 "
                 "{%0,%1,%2,%3}, {%4,%5,%6,%7}, {%8,%9}, {%0,%1,%2,%3};"
                 : "+f"(d0), "+f"(d1), "+f"(d2), "+f"(d3)
                 : "r"(a0), "r"(a1), "r"(a2), "r"(a3), "r"(b0), "r"(b1));
}
__device__ __forceinline__ void cpa16(float* dst_smem, const float* src, bool pred) {
    unsigned sa = (unsigned)__cvta_generic_to_shared(dst_smem);
    int sz = pred ? 16 : 0;
    asm volatile("cp.async.cg.shared.global [%0], [%1], 16, %2;" :: "r"(sa), "l"(src), "r"(sz));
}
#define CP_COMMIT() asm volatile("cp.async.commit_group;")
#define CP_WAIT1()  asm volatile("cp.async.wait_group 1;")

// ================= CSR build =================
__global__ void k_count(const int* __restrict__ dst, int E) {
    int i = blockIdx.x * 256 + threadIdx.x;
    if (i < E) atomicAdd(&g_cnt[dst[i]], 1);
}
// single block, warp-shuffle scan: cnt -> ptr/cur, dis = rsqrt(cnt+1)
__global__ void __launch_bounds__(1024) k_scan() {
    __shared__ int wsum[32];
    __shared__ int carry_s;
    int t = threadIdx.x, lane = t & 31, w = t >> 5;
    if (t == 0) carry_s = 0;
    __syncthreads();
    for (int base = 0; base < NN; base += 1024) {
        int i = base + t;
        int v = (i < NN) ? g_cnt[i] : 0;
        int s = v;
#pragma unroll
        for (int off = 1; off < 32; off <<= 1) {
            int x = __shfl_up_sync(0xFFFFFFFFu, s, off);
            if (lane >= off) s += x;
        }
        if (lane == 31) wsum[w] = s;
        __syncthreads();
        if (w == 0) {
            int y = wsum[lane];
#pragma unroll
            for (int off = 1; off < 32; off <<= 1) {
                int x = __shfl_up_sync(0xFFFFFFFFu, y, off);
                if (lane >= off) y += x;
            }
            wsum[lane] = y;
        }
        __syncthreads();
        int incl = s + (w > 0 ? wsum[w - 1] : 0) + carry_s;
        if (i < NN) {
            g_ptr[i] = incl - v;
            g_cur[i] = incl - v;
            g_dis[i] = rsqrtf((float)(v + 1));
        }
        __syncthreads();
        if (t == 0) carry_s += wsum[31];
        __syncthreads();
    }
    if (t == 0) g_ptr[NN] = carry_s;
}
__global__ void k_scatter(const int* __restrict__ src, const int* __restrict__ dst, int E) {
    int i = blockIdx.x * 256 + threadIdx.x;
    if (i < E) {
        int pos = atomicAdd(&g_cur[dst[i]], 1);
        g_csr[pos] = src[i];
    }
}

// ================= tf32 GEMM, cp.async double-buffered =================
// PURE C = A @ B (no dis scaling -> no dependence on CSR chain).
#define GEMM_SMEM ((2*128*36 + 2*32*72) * 4)
template<int K, int NC, int MODE>
__global__ void __launch_bounds__(256) k_gemm(const float* __restrict__ Aarg,
                                              const float* __restrict__ B, int M)
{
    const float* A = (MODE == 0) ? Aarg : (const float*)g_H1;
    float*       C = (MODE == 0) ? g_XW : g_HW;

    extern __shared__ float gsm[];
    float* Asm = gsm;                    // [2][128][36]
    float* Bsm = gsm + 2 * 128 * 36;     // [2][32][72]
#define ASF(s, r, c) Asm[(s) * (128 * 36) + (r) * 36 + (c)]
#define BSF(s, r, c) Bsm[(s) * (32 * 72) + (r) * 72 + (c)]

    int t = threadIdx.x, lane = t & 31, wid = t >> 5;
    int wm = (wid & 3) * 32, wn = (wid >> 2) * 32;
    int g = lane >> 2, q = lane & 3;
    int bm0 = blockIdx.y * 128, bn0 = blockIdx.x * 64;

    float acc[2][4][4];
#pragma unroll
    for (int i = 0; i < 2; ++i)
#pragma unroll
        for (int j = 0; j < 4; ++j)
#pragma unroll
            for (int x = 0; x < 4; ++x) acc[i][j][x] = 0.f;

    const int KT = K / 32;

    auto load_tile = [&](int kt, int s) {
#pragma unroll
        for (int it = 0; it < 4; ++it) {            // A: 128x32 = 1024 float4
            int idx = t + it * 256;
            int row = idx >> 3, c4 = (idx & 7) << 2;
            int rg = bm0 + row;
            bool ok = rg < M;
            const float* sp = &A[(size_t)(ok ? rg : 0) * K + kt * 32 + c4];
            cpa16(&ASF(s, row, c4), sp, ok);
        }
#pragma unroll
        for (int it = 0; it < 2; ++it) {            // B: 32x64 = 512 float4
            int idx = t + it * 256;
            int row = idx >> 4, c4 = (idx & 15) << 2;
            cpa16(&BSF(s, row, c4), &B[(size_t)(kt * 32 + row) * NC + bn0 + c4], true);
        }
    };

    load_tile(0, 0);
    CP_COMMIT();

    for (int kt = 0; kt < KT; ++kt) {
        int cb = kt & 1;
        if (kt + 1 < KT) load_tile(kt + 1, cb ^ 1);
        CP_COMMIT();
        CP_WAIT1();
        __syncthreads();

#pragma unroll
        for (int ks = 0; ks < 4; ++ks) {
            int kk = ks * 8;
            unsigned bf[4][2];
#pragma unroll
            for (int j = 0; j < 4; ++j) {
                bf[j][0] = f2tf(BSF(cb, kk + q,     wn + j * 8 + g));
                bf[j][1] = f2tf(BSF(cb, kk + q + 4, wn + j * 8 + g));
            }
#pragma unroll
            for (int i = 0; i < 2; ++i) {
                int r = wm + i * 16 + g;
                unsigned a0 = f2tf(ASF(cb, r,     kk + q));
                unsigned a1 = f2tf(ASF(cb, r + 8, kk + q));
                unsigned a2 = f2tf(ASF(cb, r,     kk + q + 4));
                unsigned a3 = f2tf(ASF(cb, r + 8, kk + q + 4));
#pragma unroll
                for (int j = 0; j < 4; ++j)
                    mma_tf32(acc[i][j][0], acc[i][j][1], acc[i][j][2], acc[i][j][3],
                             a0, a1, a2, a3, bf[j][0], bf[j][1]);
            }
        }
        __syncthreads();
    }

#pragma unroll
    for (int i = 0; i < 2; ++i) {
        int r0 = bm0 + wm + i * 16 + g;
#pragma unroll
        for (int j = 0; j < 4; ++j) {
            int c = bn0 + wn + j * 8 + q * 2;
            if (r0 < M)     *(float2*)&C[(size_t)r0 * NC + c]       = make_float2(acc[i][j][0], acc[i][j][1]);
            if (r0 + 8 < M) *(float2*)&C[(size_t)(r0 + 8) * NC + c] = make_float2(acc[i][j][2], acc[i][j][3]);
        }
    }
#undef ASF
#undef BSF
}

// ================= CSR aggregation (no atomics; dis applied here) =================
// H[d] = dis[d] * ( dis[d]*C[d] + sum_s dis[s]*C[s] ) + bias
// F=256: warp per node; lane owns float4 pair (feats lane*4, (lane+32)*4).
__global__ void __launch_bounds__(256) k_agg256(const float* __restrict__ bias)
{
    int gt = blockIdx.x * 256 + threadIdx.x;
    int d = gt >> 5, lane = gt & 31;
    if (d >= NN) return;
    float dd = g_dis[d];
    const float4* selfp = (const float4*)&g_XW[(size_t)d * 256];
    float4 s0 = selfp[lane], s1 = selfp[lane + 32];
    float4 a0 = make_float4(s0.x * dd, s0.y * dd, s0.z * dd, s0.w * dd);
    float4 a1 = make_float4(s1.x * dd, s1.y * dd, s1.z * dd, s1.w * dd);
    int e0 = g_ptr[d], e1 = g_ptr[d + 1];
    int e = e0;
    for (; e + 1 < e1; e += 2) {
        int n0 = g_csr[e], n1 = g_csr[e + 1];
        float ds0 = g_dis[n0], ds1 = g_dis[n1];
        const float4* p0 = (const float4*)&g_XW[(size_t)n0 * 256];
        const float4* p1 = (const float4*)&g_XW[(size_t)n1 * 256];
        float4 v00 = p0[lane], v01 = p0[lane + 32];
        float4 v10 = p1[lane], v11 = p1[lane + 32];
        a0.x += v00.x * ds0 + v10.x * ds1; a0.y += v00.y * ds0 + v10.y * ds1;
        a0.z += v00.z * ds0 + v10.z * ds1; a0.w += v00.w * ds0 + v10.w * ds1;
        a1.x += v01.x * ds0 + v11.x * ds1; a1.y += v01.y * ds0 + v11.y * ds1;
        a1.z += v01.z * ds0 + v11.z * ds1; a1.w += v01.w * ds0 + v11.w * ds1;
    }
    if (e < e1) {
        int n0 = g_csr[e];
        float ds0 = g_dis[n0];
        const float4* p0 = (const float4*)&g_XW[(size_t)n0 * 256];
        float4 v00 = p0[lane], v01 = p0[lane + 32];
        a0.x += v00.x * ds0; a0.y += v00.y * ds0; a0.z += v00.z * ds0; a0.w += v00.w * ds0;
        a1.x += v01.x * ds0; a1.y += v01.y * ds0; a1.z += v01.z * ds0; a1.w += v01.w * ds0;
    }
    float4 b0 = ((const float4*)bias)[lane], b1 = ((const float4*)bias)[lane + 32];
    float4* hp = (float4*)&g_H1[(size_t)d * 256];
    hp[lane]      = make_float4(a0.x * dd + b0.x, a0.y * dd + b0.y, a0.z * dd + b0.z, a0.w * dd + b0.w);
    hp[lane + 32] = make_float4(a1.x * dd + b1.x, a1.y * dd + b1.y, a1.z * dd + b1.z, a1.w * dd + b1.w);
}
// F=64: warp per node, lane holds float2.
__global__ void __launch_bounds__(256) k_agg64(const float* __restrict__ bias)
{
    int gt = blockIdx.x * 256 + threadIdx.x;
    int d = gt >> 5, lane = gt & 31;
    if (d >= NN) return;
    float dd = g_dis[d];
    float2 sv = *(const float2*)&g_HW[(size_t)d * 64 + lane * 2];
    float2 acc = make_float2(sv.x * dd, sv.y * dd);
    int e0 = g_ptr[d], e1 = g_ptr[d + 1];
    int e = e0;
    for (; e + 1 < e1; e += 2) {
        int n0 = g_csr[e], n1 = g_csr[e + 1];
        float ds0 = g_dis[n0], ds1 = g_dis[n1];
        float2 v0 = *(const float2*)&g_HW[(size_t)n0 * 64 + lane * 2];
        float2 v1 = *(const float2*)&g_HW[(size_t)n1 * 64 + lane * 2];
        acc.x += v0.x * ds0 + v1.x * ds1; acc.y += v0.y * ds0 + v1.y * ds1;
    }
    if (e < e1) {
        int n0 = g_csr[e];
        float ds0 = g_dis[n0];
        float2 v = *(const float2*)&g_HW[(size_t)n0 * 64 + lane * 2];
        acc.x += v.x * ds0; acc.y += v.y * ds0;
    }
    float2 b = *(const float2*)&bias[lane * 2];
    *(float2*)&g_Z[(size_t)d * 64 + lane * 2] = make_float2(acc.x * dd + b.x, acc.y * dd + b.y);
}

// ================= decoder: Y = sigmoid(Z Z^T), tf32, triangular grid =================
#define DEC_SMEM (128*68*4 + 64*136*4)   // 69632 B; T[128][132] reuses it
__global__ void __launch_bounds__(256) k_decode(float* __restrict__ Y, int M)
{
    int k = blockIdx.x;
    int bi = (int)((2.0f * NB + 1.0f - sqrtf((2.0f * NB + 1.0f) * (2.0f * NB + 1.0f) - 8.0f * k)) * 0.5f);
    if (bi < 0) bi = 0;
    while (bi * NB - bi * (bi - 1) / 2 > k) --bi;
    while ((bi + 1) * NB - (bi + 1) * bi / 2 <= k) ++bi;
    int bj = bi + (k - (bi * NB - bi * (bi - 1) / 2));

    extern __shared__ unsigned char sraw[];
    unsigned (*As)[68]  = (unsigned(*)[68])sraw;                  // [128][68]
    unsigned (*Bs)[136] = (unsigned(*)[136])(sraw + 128*68*4);    // [64][136]
    float* T = (float*)sraw;                                      // [128][132] phase 2

    int t = threadIdx.x, lane = t & 31, wid = t >> 5;
    int wm = (wid & 3) * 32, wn = (wid >> 2) * 64;
    int g = lane >> 2, q = lane & 3;
    int r0b = bi * 128, c0b = bj * 128;

#pragma unroll
    for (int it = 0; it < 8; ++it) {
        int idx = t + it * 256;           // 2048: 128 rows x 16 float4
        int row = idx >> 4, c4 = (idx & 15) << 2;
        float4 v = make_float4(0.f, 0.f, 0.f, 0.f);
        if (r0b + row < M) v = *(const float4*)&g_Z[(r0b + row) * 64 + c4];
        *(uint4*)&As[row][c4] = make_uint4(f2tf(v.x), f2tf(v.y), f2tf(v.z), f2tf(v.w));
    }
#pragma unroll
    for (int it = 0; it < 8; ++it) {
        int idx = t + it * 256;
        int col = idx & 127, c4 = (idx >> 7) << 2;
        float4 v = make_float4(0.f, 0.f, 0.f, 0.f);
        if (c0b + col < M) v = *(const float4*)&g_Z[(c0b + col) * 64 + c4];
        Bs[c4 + 0][col] = f2tf(v.x); Bs[c4 + 1][col] = f2tf(v.y);
        Bs[c4 + 2][col] = f2tf(v.z); Bs[c4 + 3][col] = f2tf(v.w);
    }
    __syncthreads();

    float acc[2][8][4];
#pragma unroll
    for (int i = 0; i < 2; ++i)
#pragma unroll
        for (int j = 0; j < 8; ++j)
#pragma unroll
            for (int x = 0; x < 4; ++x) acc[i][j][x] = 0.f;

#pragma unroll
    for (int ks = 0; ks < 8; ++ks) {
        int kk = ks * 8;
        unsigned bf[8][2];
#pragma unroll
        for (int j = 0; j < 8; ++j) {
            bf[j][0] = Bs[kk + q][wn + j * 8 + g];
            bf[j][1] = Bs[kk + q + 4][wn + j * 8 + g];
        }
#pragma unroll
        for (int i = 0; i < 2; ++i) {
            int r = wm + i * 16 + g;
            unsigned a0 = As[r][kk + q],     a1 = As[r + 8][kk + q];
            unsigned a2 = As[r][kk + q + 4], a3 = As[r + 8][kk + q + 4];
#pragma unroll
            for (int j = 0; j < 8; ++j)
                mma_tf32(acc[i][j][0], acc[i][j][1], acc[i][j][2], acc[i][j][3],
                         a0, a1, a2, a3, bf[j][0], bf[j][1]);
        }
    }

#pragma unroll
    for (int i = 0; i < 2; ++i)
#pragma unroll
        for (int j = 0; j < 8; ++j)
#pragma unroll
            for (int x = 0; x < 4; ++x)
                acc[i][j][x] = 1.0f / (1.0f + __expf(-acc[i][j][x]));

#pragma unroll
    for (int i = 0; i < 2; ++i) {
        int r = r0b + wm + i * 16 + g;
#pragma unroll
        for (int j = 0; j < 8; ++j) {
            int c = c0b + wn + j * 8 + q * 2;
            if (c < M) {
                if (r < M)     *(float2*)&Y[(size_t)r * M + c]       = make_float2(acc[i][j][0], acc[i][j][1]);
                if (r + 8 < M) *(float2*)&Y[(size_t)(r + 8) * M + c] = make_float2(acc[i][j][2], acc[i][j][3]);
            }
        }
    }

    if (bi != bj) {
        __syncthreads();
#pragma unroll
        for (int i = 0; i < 2; ++i) {
#pragma unroll
            for (int j = 0; j < 8; ++j) {
                int cc = wn + j * 8 + q * 2;
                int rr = wm + i * 16 + g;
                T[cc * 132 + rr]           = acc[i][j][0];
                T[(cc + 1) * 132 + rr]     = acc[i][j][1];
                T[cc * 132 + rr + 8]       = acc[i][j][2];
                T[(cc + 1) * 132 + rr + 8] = acc[i][j][3];
            }
        }
        __syncthreads();
#pragma unroll
        for (int it = 0; it < 16; ++it) {
            int idx = t + it * 256;
            int cc = idx >> 5, rc = (idx & 31) << 2;
            int crow = c0b + cc;
            if (crow < M) {
                float4 v = *(const float4*)&T[cc * 132 + rc];
                if (r0b + rc + 3 < M) {
                    *(float4*)&Y[(size_t)crow * M + r0b + rc] = v;
                } else {
                    float vv[4] = {v.x, v.y, v.z, v.w};
                    for (int j = 0; j < 4; ++j)
                        if (r0b + rc + j < M) Y[(size_t)crow * M + r0b + rc + j] = vv[j];
                }
            }
        }
    }
}

// ================= launch =================
extern "C" void kernel_launch(void* const* d_in, const int* in_sizes, int n_in,
                              void* d_out, int out_size)
{
    const float* X  = (const float*)d_in[0];
    const int*   ei = (const int*)  d_in[1];
    const float* W1 = (const float*)d_in[2];
    const float* b1 = (const float*)d_in[3];
    const float* W2 = (const float*)d_in[4];
    const float* b2 = (const float*)d_in[5];
    float* Y = (float*)d_out;

    int E = in_sizes[1] / 2;
    if (E > NE) E = NE;
    const int* src = ei;
    const int* dst = ei + E;

    static bool init_done = false;
    static cudaStream_t s2;
    static cudaEvent_t evA, evB;
    static void* p_cnt;
    if (!init_done) {
        cudaFuncSetAttribute(k_decode, cudaFuncAttributeMaxDynamicSharedMemorySize, DEC_SMEM);
        cudaFuncSetAttribute(k_gemm<F0, F1, 0>, cudaFuncAttributeMaxDynamicSharedMemorySize, GEMM_SMEM);
        cudaFuncSetAttribute(k_gemm<F1, F2, 1>, cudaFuncAttributeMaxDynamicSharedMemorySize, GEMM_SMEM);
        cudaStreamCreateWithFlags(&s2, cudaStreamNonBlocking);
        cudaEventCreateWithFlags(&evA, cudaEventDisableTiming);
        cudaEventCreateWithFlags(&evB, cudaEventDisableTiming);
        cudaGetSymbolAddress(&p_cnt, g_cnt);
        init_done = true;
    }

    // fork: gemm1 (X,W1 only — no g_dis read now) on s2; CSR build on stream 0
    cudaEventRecord(evA, 0);
    cudaStreamWaitEvent(s2, evA, 0);

    dim3 g1(F1 / 64, (NN + 127) / 128);
    k_gemm<F0, F1, 0><<<g1, 256, GEMM_SMEM, s2>>>(X, W1, NN);
    cudaEventRecord(evB, s2);

    cudaMemsetAsync(p_cnt, 0, NN * sizeof(int), 0);
    k_count  <<<(E + 255) / 256, 256>>>(dst, E);
    k_scan   <<<1, 1024>>>();
    k_scatter<<<(E + 255) / 256, 256>>>(src, dst, E);

    // join: agg256 needs gemm1 (s2) + CSR/dis (stream 0)
    cudaStreamWaitEvent(0, evB, 0);

    k_agg256<<<(NN * 32 + 255) / 256, 256>>>(b1);

    dim3 g2(F2 / 64, (NN + 127) / 128);
    k_gemm<F1, F2, 1><<<g2, 256, GEMM_SMEM>>>(nullptr, W2, NN);
    k_agg64<<<(NN * 32 + 255) / 256, 256>>>(b2);

    k_decode<<<NB * (NB + 1) / 2, 256, DEC_SMEM>>>(Y, NN);
}